// round 1
// baseline (speedup 1.0000x reference)
#include <cuda_runtime.h>
#include <math_constants.h>

#define BB 4
#define CC 64
#define WDIM 64
#define NN 4096

#define DQ 10       // effective dot dims (8 + col + row)
#define QW 4        // queries per warp
#define WARPS 8
#define BLOCK_Q (QW*WARPS)   // 32 queries per block
#define KT 64       // key tile

// Scratch (device globals; no allocation allowed)
__device__ float g_QP[BB][NN][12];    // q' per query (padded to 12)
__device__ float g_KP[BB][DQ][NN];    // k' channel-major
__device__ float g_VT[BB][NN][CC];    // v transposed [key][channel]

// ---------------------------------------------------------------------------
// Prep: 1x1 convs -> q', k', v.  64 pixels per block, 64 threads.
// ---------------------------------------------------------------------------
__global__ __launch_bounds__(64) void prep_kernel(
    const float* __restrict__ x,
    const float* __restrict__ Wq, const float* __restrict__ bq,
    const float* __restrict__ Wk, const float* __restrict__ bk,
    const float* __restrict__ Wv, const float* __restrict__ bv)
{
    __shared__ float xs[CC][64];
    __shared__ float wv_s[CC][CC];
    __shared__ float wq_s[8][CC];
    __shared__ float wk_s[8][CC];
    __shared__ float bv_s[CC];
    __shared__ float bq_s[8], bk_s[8];

    int b  = blockIdx.x / (NN/64);
    int n0 = (blockIdx.x % (NN/64)) * 64;
    int t  = threadIdx.x;

    #pragma unroll 8
    for (int c = 0; c < CC; c++)
        xs[c][t] = x[(b*CC + c)*NN + n0 + t];

    for (int i = t; i < CC*CC; i += 64) wv_s[i/CC][i%CC] = Wv[i];
    for (int i = t; i < 8*CC;  i += 64) { wq_s[i/CC][i%CC] = Wq[i]; wk_s[i/CC][i%CC] = Wk[i]; }
    if (t < CC) bv_s[t] = bv[t];
    if (t < 8)  { bq_s[t] = bq[t]; bk_s[t] = bk[t]; }
    __syncthreads();

    float accv[CC];
    float accq[8], acck[8];
    #pragma unroll
    for (int e = 0; e < CC; e++) accv[e] = 0.f;
    #pragma unroll
    for (int d = 0; d < 8; d++) { accq[d] = 0.f; acck[d] = 0.f; }

    for (int c = 0; c < CC; c++) {
        float xc = xs[c][t];
        #pragma unroll
        for (int e = 0; e < CC; e++) accv[e] = fmaf(wv_s[e][c], xc, accv[e]);
        #pragma unroll
        for (int d = 0; d < 8; d++) {
            accq[d] = fmaf(wq_s[d][c], xc, accq[d]);
            acck[d] = fmaf(wk_s[d][c], xc, acck[d]);
        }
    }

    int n = n0 + t;
    #pragma unroll
    for (int d = 0; d < 8; d++) g_QP[b][n][d] = accq[d] + bq_s[d];
    g_QP[b][n][8]  = accq[0] + bq_s[0];   // q0 -> pairs with col_m key channel
    g_QP[b][n][9]  = accq[1] + bq_s[1];   // q1 -> pairs with row_m key channel
    g_QP[b][n][10] = 0.f;
    g_QP[b][n][11] = 0.f;

    #pragma unroll
    for (int d = 0; d < 8; d++) g_KP[b][d][n] = acck[d] + bk_s[d];
    g_KP[b][8][n] = (float)(n % WDIM);    // col_m
    g_KP[b][9][n] = (float)(n / WDIM);    // row_m

    #pragma unroll
    for (int e = 0; e < CC; e++) g_VT[b][n][e] = accv[e] + bv_s[e];
}

// ---------------------------------------------------------------------------
// Flash attention: 512 blocks, 256 threads (8 warps x 4 queries/warp).
// Relative-position folded into key channels 8,9 (query-constant part
// cancels in softmax).
// ---------------------------------------------------------------------------
__global__ __launch_bounds__(256) void attn_kernel(float* __restrict__ out)
{
    __shared__ float kp_s[DQ][KT];
    __shared__ float v_s[KT][CC];
    __shared__ float p_s[WARPS][QW][KT];
    __shared__ float q_s[BLOCK_Q][12];

    int b  = blockIdx.x / (NN/BLOCK_Q);
    int n0 = (blockIdx.x % (NN/BLOCK_Q)) * BLOCK_Q;
    int t  = threadIdx.x;
    int w  = t >> 5;
    int l  = t & 31;

    // stage q' for this block's queries
    for (int i = t; i < BLOCK_Q*12; i += 256)
        (&q_s[0][0])[i] = (&g_QP[b][n0][0])[i];
    __syncthreads();

    float qr[QW][DQ];
    #pragma unroll
    for (int qi = 0; qi < QW; qi++)
        #pragma unroll
        for (int d = 0; d < DQ; d++)
            qr[qi][d] = q_s[w*QW + qi][d];

    float acc[QW][2];
    float Mx[QW], Sm[QW];
    #pragma unroll
    for (int qi = 0; qi < QW; qi++) {
        acc[qi][0] = 0.f; acc[qi][1] = 0.f;
        Mx[qi] = -1e30f;  Sm[qi] = 0.f;
    }

    const float L2E = 1.44269504088896f;

    for (int kt = 0; kt < NN/KT; kt++) {
        int m0 = kt * KT;
        __syncthreads();
        // stage k' tile (channel-major) and v tile
        for (int i = t; i < DQ*KT; i += 256) {
            int d = i / KT, j = i % KT;
            kp_s[d][j] = g_KP[b][d][m0 + j];
        }
        for (int i = t; i < KT*CC/4; i += 256) {
            int row = i / (CC/4), c4 = i % (CC/4);
            ((float4*)v_s[row])[c4] = ((const float4*)g_VT[b][m0 + row])[c4];
        }
        __syncthreads();

        // scores: lane l covers keys m0+l and m0+32+l for QW queries
        float s0[QW], s1[QW];
        #pragma unroll
        for (int qi = 0; qi < QW; qi++) { s0[qi] = 0.f; s1[qi] = 0.f; }
        #pragma unroll
        for (int d = 0; d < DQ; d++) {
            float k0 = kp_s[d][l];
            float k1 = kp_s[d][32 + l];
            #pragma unroll
            for (int qi = 0; qi < QW; qi++) {
                s0[qi] = fmaf(qr[qi][d], k0, s0[qi]);
                s1[qi] = fmaf(qr[qi][d], k1, s1[qi]);
            }
        }

        // online softmax update
        #pragma unroll
        for (int qi = 0; qi < QW; qi++) {
            float tm = fmaxf(s0[qi], s1[qi]);
            #pragma unroll
            for (int o = 16; o > 0; o >>= 1)
                tm = fmaxf(tm, __shfl_xor_sync(0xffffffffu, tm, o));
            float newM  = fmaxf(Mx[qi], tm);
            float alpha = exp2f((Mx[qi] - newM) * L2E);
            Mx[qi] = newM;
            float p0 = exp2f((s0[qi] - newM) * L2E);
            float p1 = exp2f((s1[qi] - newM) * L2E);
            Sm[qi] = Sm[qi]*alpha + p0 + p1;
            acc[qi][0] *= alpha;
            acc[qi][1] *= alpha;
            p_s[w][qi][l]      = p0;
            p_s[w][qi][32 + l] = p1;
        }
        __syncwarp();

        // PV accumulate: lane owns channels 2l, 2l+1
        #pragma unroll 4
        for (int j4 = 0; j4 < KT/4; j4++) {
            float4 p4[QW];
            #pragma unroll
            for (int qi = 0; qi < QW; qi++)
                p4[qi] = ((float4*)p_s[w][qi])[j4];
            #pragma unroll
            for (int jj = 0; jj < 4; jj++) {
                float2 v2 = ((float2*)v_s[j4*4 + jj])[l];
                #pragma unroll
                for (int qi = 0; qi < QW; qi++) {
                    float pv = (jj == 0) ? p4[qi].x : (jj == 1) ? p4[qi].y
                             : (jj == 2) ? p4[qi].z : p4[qi].w;
                    acc[qi][0] = fmaf(pv, v2.x, acc[qi][0]);
                    acc[qi][1] = fmaf(pv, v2.y, acc[qi][1]);
                }
            }
        }
    }

    // finalize
    #pragma unroll
    for (int qi = 0; qi < QW; qi++) {
        float s = Sm[qi];
        #pragma unroll
        for (int o = 16; o > 0; o >>= 1)
            s += __shfl_xor_sync(0xffffffffu, s, o);
        float inv = 1.0f / s;
        int n = n0 + w*QW + qi;
        out[(b*CC + 2*l    )*NN + n] = acc[qi][0] * inv;
        out[(b*CC + 2*l + 1)*NN + n] = acc[qi][1] * inv;
    }
}

extern "C" void kernel_launch(void* const* d_in, const int* in_sizes, int n_in,
                              void* d_out, int out_size)
{
    const float* x  = (const float*)d_in[0];
    const float* Wq = (const float*)d_in[1];
    const float* bq = (const float*)d_in[2];
    const float* Wk = (const float*)d_in[3];
    const float* bk = (const float*)d_in[4];
    const float* Wv = (const float*)d_in[5];
    const float* bv = (const float*)d_in[6];
    float* out = (float*)d_out;

    prep_kernel<<<BB*(NN/64), 64>>>(x, Wq, bq, Wk, bk, Wv, bv);
    attn_kernel<<<BB*(NN/BLOCK_Q), 256>>>(out);
}